// round 13
// baseline (speedup 1.0000x reference)
#include <cuda_runtime.h>
#include <cuda_bf16.h>
#include <cstdint>

// ============================================================================
// ComplexConv2Deffangle via warp-level bf16 3-term split MMA (m16n8k16),
// 4-chunk pipeline, 3 blocks/SM, m4n2 warp split (reduced smem B traffic),
// p1 log folded into staging (no in-place log pass).
//   path0 (rot): depthwise 3x3 (w1^2/sum)  -> 1x1 (w2^2/sum)
//   path1 (abs): log(x+eps) -> depthwise (w1^2/rowsum) -> 1x1 (w2^2/rowsum) -> exp
// x: (32,2,64,64,64) f32, w1: (64,9), w2: (128,64) -> out: (32,2,128,62,62)
// Per block: D[128 och][128 n] = W[128][64] * V[64][128]; v = hi+lo bf16,
// D = Wh*Vh + Wh*Vl + Wl*Vh.
// ============================================================================

#define EPS 1e-6f
#define C_IN 64
#define C_OUT 128
#define HH 64
#define WW 64
#define OX 62
#define OY 62
#define LTOT (OX * OY)           // 3844

#define XCH 300                  // xin channel stride (floats), 1200 B
#define XRW 68                   // xin row stride (floats), 272 B

// smem byte offsets
#define OFF_BQ   0               // uint4[4*516]: B quads per chunk     33,024 B
#define OFF_X0   33024           // xin buf0 (16 ch x 4 rows)           19,200 B
#define OFF_X1   52224           // xin buf1                            19,200 B
#define OFF_W1S  71424           // float[64][9]                         2,304 B
#define SMEM_TOTAL 73728         // -> 3 blocks/SM (216 KB / 228 KB)

// A fragments pre-packed for m16n8k16.bf16, hi/lo interleaved:
// g_w2b[p][cc][kk][m_tile][lane][hl]; chunk g = cc*2 + kk covers ch g*16..+15
__device__ float4 g_w2b[2][2][2][8][32][2];
__device__ float  g_w1n[2][C_IN][9];

// ---------------------------------------------------------------------------
__device__ __forceinline__ uint32_t smem_u32(const void* p) {
    uint32_t a;
    asm("{ .reg .u64 t; cvta.to.shared.u64 t, %1; cvt.u32.u64 %0, t; }"
        : "=r"(a) : "l"(p));
    return a;
}
// returns bf16x2 {upper=hi_e, lower=lo_e}
__device__ __forceinline__ uint32_t pack_bf(float lo_e, float hi_e) {
    uint32_t d;
    asm("cvt.rn.bf16x2.f32 %0, %1, %2;" : "=r"(d) : "f"(hi_e), "f"(lo_e));
    return d;
}
__device__ __forceinline__ float bf16rn(float x) {
    uint32_t d;
    asm("cvt.rn.bf16x2.f32 %0, %1, %1;" : "=r"(d) : "f"(x));
    return __uint_as_float(d << 16);
}
__device__ __forceinline__ void mma_bf16(float* acc, uint32_t a0, uint32_t a1,
                                         uint32_t a2, uint32_t a3,
                                         uint32_t b0, uint32_t b1) {
    asm volatile(
        "mma.sync.aligned.m16n8k16.row.col.f32.bf16.bf16.f32 "
        "{%0,%1,%2,%3}, {%4,%5,%6,%7}, {%8,%9}, {%0,%1,%2,%3};"
        : "+f"(acc[0]), "+f"(acc[1]), "+f"(acc[2]), "+f"(acc[3])
        : "r"(a0), "r"(a1), "r"(a2), "r"(a3), "r"(b0), "r"(b1));
}
__device__ __forceinline__ void cp16(uint32_t dst, const void* src) {
    asm volatile("cp.async.cg.shared.global [%0], [%1], 16;"
                 :: "r"(dst), "l"(src) : "memory");
}
#define CP_COMMIT() asm volatile("cp.async.commit_group;" ::: "memory")
#define CP_WAIT(n)  asm volatile("cp.async.wait_group %0;" :: "n"(n) : "memory")

// xin addressing (floats): channel cl in 0..15, row rr, col f.
// shift (cl>>1)*4 makes 16B-columns a permutation per quarter-warp.
__device__ __forceinline__ int xoff(int cl, int rr, int f) {
    return cl * XCH + (cl >> 1) * 4 + rr * XRW + f;
}

// ---------------------------------------------------------------------------
// Prep kernel: normalize weights, bf16-split, pack mma A fragments.
// ---------------------------------------------------------------------------
__global__ void prep_weights_kernel(const float* __restrict__ w1,
                                    const float* __restrict__ w2) {
    __shared__ float red[256];
    __shared__ float s1_sh, s2_sh;
    __shared__ float s1r[C_IN];
    __shared__ float s2r[C_OUT];
    int tid = threadIdx.x;

    float a = 0.f;
    for (int i = tid; i < C_IN * 9; i += 256) { float t = w1[i]; a += t * t; }
    red[tid] = a; __syncthreads();
    for (int s = 128; s > 0; s >>= 1) { if (tid < s) red[tid] += red[tid + s]; __syncthreads(); }
    if (tid == 0) s1_sh = red[0];
    __syncthreads();

    a = 0.f;
    for (int i = tid; i < C_OUT * C_IN; i += 256) { float t = w2[i]; a += t * t; }
    red[tid] = a; __syncthreads();
    for (int s = 128; s > 0; s >>= 1) { if (tid < s) red[tid] += red[tid + s]; __syncthreads(); }
    if (tid == 0) s2_sh = red[0];

    if (tid < C_IN) {
        float s = 0.f;
        for (int k = 0; k < 9; k++) { float t = w1[tid * 9 + k]; s += t * t; }
        s1r[tid] = s;
    }
    if (tid < C_OUT) {
        float s = 0.f;
        for (int c = 0; c < C_IN; c++) { float t = w2[tid * C_IN + c]; s += t * t; }
        s2r[tid] = s;
    }
    __syncthreads();

    float inv_s1 = 1.f / s1_sh;
    float inv_s2 = 1.f / s2_sh;

    for (int i = tid; i < C_IN * 9; i += 256) {
        int c = i / 9;
        float t = w1[i]; float t2 = t * t;
        ((float*)g_w1n[0])[i] = t2 * inv_s1;
        ((float*)g_w1n[1])[i] = t2 / s1r[c];
    }

    // A fragments: j indexes (p, cc, kk, m_tile, lane)
    float4* flat = (float4*)g_w2b;
    for (int j = tid; j < 2048; j += 256) {
        int lane = j & 31;
        int wq   = (j >> 5) & 7;
        int kk   = (j >> 8) & 1;
        int cc   = (j >> 9) & 1;
        int p    = j >> 10;
        int qq = lane >> 2, rr2 = lane & 3;
        int cb = cc * 32 + kk * 16 + 2 * rr2;
        int ms[2] = {wq * 16 + qq, wq * 16 + qq + 8};
        uint32_t ah[4], al[4];
        #pragma unroll
        for (int i = 0; i < 4; i++) {
            int m  = ms[i & 1];
            int c0 = cb + (i >> 1) * 8;
            float t0 = w2[m * C_IN + c0];
            float t1 = w2[m * C_IN + c0 + 1];
            float v0 = (p == 0) ? t0 * t0 * inv_s2 : t0 * t0 / s2r[m];
            float v1 = (p == 0) ? t1 * t1 * inv_s2 : t1 * t1 / s2r[m];
            float h0 = bf16rn(v0), h1 = bf16rn(v1);
            ah[i] = pack_bf(h0, h1);           // lower = k even
            al[i] = pack_bf(v0 - h0, v1 - h1);
        }
        flat[j * 2 + 0] = make_float4(__uint_as_float(ah[0]), __uint_as_float(ah[1]),
                                      __uint_as_float(ah[2]), __uint_as_float(ah[3]));
        flat[j * 2 + 1] = make_float4(__uint_as_float(al[0]), __uint_as_float(al[1]),
                                      __uint_as_float(al[2]), __uint_as_float(al[3]));
    }
}

// ---------------------------------------------------------------------------
// Main kernel: grid (31 row-pairs, 32 batch, 2 path), 256 threads, 3 blk/SM.
// ---------------------------------------------------------------------------
__global__ __launch_bounds__(256, 3)
void cce_mma_kernel(const float* __restrict__ x, float* __restrict__ out) {
    extern __shared__ char smem[];
    const uint32_t sb = smem_u32(smem);
    uint4*  BQ4 = (uint4*)(smem + OFF_BQ);
    uint2*  BQ2 = (uint2*)(smem + OFF_BQ);
    float*  w1s = (float*)(smem + OFF_W1S);

    const int tid  = threadIdx.x;
    const int warp = tid >> 5;
    const int lane = tid & 31;
    const int q    = lane >> 2;              // groupID
    const int r    = lane & 3;               // threadInGroup
    const int r0   = blockIdx.x * 2;
    const int b    = blockIdx.y;
    const int p    = blockIdx.z;

    const float* xbase = x + (size_t)(b * 2 + p) * (C_IN * HH * WW) + r0 * WW;

    // per-thread staging coords (same for every chunk)
    const int scl = tid >> 6;                // base channel row of 4 handled
    const int sqq = tid & 63;

    // cp.async staging for chunk g (p==0 path)
    auto issue_chunk = [&](int g) {
        const uint32_t xo = sb + ((g & 1) ? OFF_X1 : OFF_X0);
        const float* xc = xbase + (size_t)(g * 16) * (HH * WW);
        #pragma unroll
        for (int i = 0; i < 4; i++) {
            int cl = scl + i * 4;
            cp16(xo + (uint32_t)xoff(cl, sqq >> 4, (sqq & 15) * 4) * 4,
                 xc + (size_t)cl * (HH * WW) + sqq * 4);
        }
        CP_COMMIT();
    };
    // manual LDG prefetch (p==1 path)
    auto ldg_chunk = [&](int g, float4* pf) {
        const float* xc = xbase + (size_t)(g * 16) * (HH * WW);
        #pragma unroll
        for (int i = 0; i < 4; i++) {
            int cl = scl + i * 4;
            pf[i] = *(const float4*)(xc + (size_t)cl * (HH * WW) + sqq * 4);
        }
    };

    float4 pfA[4], pfB[4];
    if (p == 0) {
        issue_chunk(0);
        issue_chunk(1);
    } else {
        ldg_chunk(0, pfA);
        ldg_chunk(1, pfB);
    }
    for (int i = tid; i < C_IN * 9; i += 256) w1s[i] = ((const float*)g_w1n[p])[i];

    // dw decomposition: hp = ch-offset half {0,8}, rp = r-slot, 4 cols
    const int hp  = tid & 1;
    const int rp  = (tid >> 1) & 3;
    const int nb  = tid >> 3;                // 0..31
    const int n0  = nb * 4;
    const int rl0 = n0 >> 6;
    const int l0  = n0 & 63;                 // 4-aligned

    // ========== phase 1: staging + depthwise, 4 chunks of 16 channels ======
    #pragma unroll
    for (int g = 0; g < 4; g++) {
        float* xin = (float*)(smem + ((g & 1) ? OFF_X1 : OFF_X0));

        if (p == 0) {
            if (g < 3) { CP_WAIT(1); } else { CP_WAIT(0); }
        } else {
            // write prefetched chunk with log applied, then refill regs
            float4* pf = (g & 1) ? pfB : pfA;
            #pragma unroll
            for (int i = 0; i < 4; i++) {
                int cl = scl + i * 4;
                float4 v = pf[i];
                v.x = __logf(v.x + EPS); v.y = __logf(v.y + EPS);
                v.z = __logf(v.z + EPS); v.w = __logf(v.w + EPS);
                *(float4*)(xin + xoff(cl, sqq >> 4, (sqq & 15) * 4)) = v;
            }
            if (g < 2) ldg_chunk(g + 2, pf);
        }
        __syncthreads();                     // staged chunk visible

        // depthwise 3x3: 2 channels x 4 cols per thread
        float dv[2][4];
        #pragma unroll
        for (int i = 0; i < 2; i++)
            #pragma unroll
            for (int j = 0; j < 4; j++) dv[i][j] = 0.f;

        #pragma unroll
        for (int ch2 = 0; ch2 < 2; ch2++) {
            int cl = 2 * rp + 8 * hp + ch2;
            const float* wc = w1s + (g * 16 + cl) * 9;
            float* av = dv[ch2];
            #pragma unroll
            for (int rr = 0; rr < 3; rr++) {
                const float* xr = xin + xoff(cl, rl0 + rr, 0);
                float4 u0 = *(const float4*)(xr + l0);
                float4 u1 = *(const float4*)(xr + l0 + 4);
                float f[8] = {u0.x,u0.y,u0.z,u0.w, u1.x,u1.y,u1.z,u1.w};
                float w0 = wc[rr * 3 + 0], w1v = wc[rr * 3 + 1], w2v = wc[rr * 3 + 2];
                #pragma unroll
                for (int ci = 0; ci < 4; ci++)
                    av[ci] = fmaf(f[ci], w0,
                             fmaf(f[ci + 1], w1v,
                             fmaf(f[ci + 2], w2v, av[ci])));
            }
        }
        // bf16 split + store half-quads {h01, l01} (hp selects quad half)
        #pragma unroll
        for (int ci = 0; ci < 4; ci++) {
            int n = n0 + ci;
            float v0 = dv[0][ci], v1 = dv[1][ci];
            float h0 = bf16rn(v0), h1 = bf16rn(v1);
            BQ2[(g * 516 + n * 4 + rp) * 2 + hp] =
                make_uint2(pack_bf(h0, h1), pack_bf(v0 - h0, v1 - h1));
        }
        __syncthreads();                     // buffer free + BQ[g] visible

        if (p == 0 && g < 2) issue_chunk(g + 2);
    }

    // ========== phase 2: MMA, m4n2 warp split, 2 rounds of 4 n-tiles =======
    // warp: mw = warp&3 -> och 32*mw..+31 (m-tiles 2mw, 2mw+1);
    //       nh = warp>>2 -> out row r0+nh (n 64*nh..+63).
    const int mw = warp & 3;
    const int nh = warp >> 2;
    float* obase = out + (size_t)(b * 2 + p) * (C_OUT * LTOT) + (size_t)r0 * OY;

    #pragma unroll
    for (int round = 0; round < 2; round++) {
        float acc[32];
        #pragma unroll
        for (int i = 0; i < 32; i++) acc[i] = 0.f;

        #pragma unroll
        for (int g = 0; g < 4; g++) {
            const float4* wgA = &g_w2b[p][g >> 1][g & 1][2 * mw][lane][0];
            const float4* wgB = &g_w2b[p][g >> 1][g & 1][2 * mw + 1][lane][0];
            float4 AH0 = wgA[0], AL0 = wgA[1];
            float4 AH1 = wgB[0], AL1 = wgB[1];
            uint32_t a0h = __float_as_uint(AH0.x), a1h = __float_as_uint(AH0.y);
            uint32_t a2h = __float_as_uint(AH0.z), a3h = __float_as_uint(AH0.w);
            uint32_t a0l = __float_as_uint(AL0.x), a1l = __float_as_uint(AL0.y);
            uint32_t a2l = __float_as_uint(AL0.z), a3l = __float_as_uint(AL0.w);
            uint32_t c0h = __float_as_uint(AH1.x), c1h = __float_as_uint(AH1.y);
            uint32_t c2h = __float_as_uint(AH1.z), c3h = __float_as_uint(AH1.w);
            uint32_t c0l = __float_as_uint(AL1.x), c1l = __float_as_uint(AL1.y);
            uint32_t c2l = __float_as_uint(AL1.z), c3l = __float_as_uint(AL1.w);
            const uint4* bq = BQ4 + g * 516 + (nh * 8 + round * 4) * 32 + q * 4 + r;
            #pragma unroll
            for (int t = 0; t < 4; t++) {
                uint4 B = bq[t * 32];
                mma_bf16(acc + t * 4,      a0h, a1h, a2h, a3h, B.x, B.z);
                mma_bf16(acc + t * 4,      a0h, a1h, a2h, a3h, B.y, B.w);
                mma_bf16(acc + t * 4,      a0l, a1l, a2l, a3l, B.x, B.z);
                mma_bf16(acc + 16 + t * 4, c0h, c1h, c2h, c3h, B.x, B.z);
                mma_bf16(acc + 16 + t * 4, c0h, c1h, c2h, c3h, B.y, B.w);
                mma_bf16(acc + 16 + t * 4, c0l, c1l, c2l, c3l, B.x, B.z);
            }
        }

        // epilogue: out row r0+nh, cols round*32 + t*8 + 2r
        #pragma unroll
        for (int tm2 = 0; tm2 < 2; tm2++) {
            #pragma unroll
            for (int t = 0; t < 4; t++) {
                int colb = round * 32 + t * 8 + 2 * r;
                if (colb < OY) {
                    int m = 32 * mw + 16 * tm2 + q;
                    float2 v0 = make_float2(acc[tm2 * 16 + t * 4 + 0],
                                            acc[tm2 * 16 + t * 4 + 1]);
                    float2 v1 = make_float2(acc[tm2 * 16 + t * 4 + 2],
                                            acc[tm2 * 16 + t * 4 + 3]);
                    if (p == 1) {
                        v0.x = __expf(v0.x); v0.y = __expf(v0.y);
                        v1.x = __expf(v1.x); v1.y = __expf(v1.y);
                    }
                    float* addr = obase + nh * OY + colb;
                    *(float2*)(addr + (size_t)m * LTOT)       = v0;
                    *(float2*)(addr + (size_t)(m + 8) * LTOT) = v1;
                }
            }
        }
    }
}

// ---------------------------------------------------------------------------
extern "C" void kernel_launch(void* const* d_in, const int* in_sizes, int n_in,
                              void* d_out, int out_size) {
    const float* x  = (const float*)d_in[0];
    const float* w1 = (const float*)d_in[1];
    const float* w2 = (const float*)d_in[2];
    float* out = (float*)d_out;

    prep_weights_kernel<<<1, 256>>>(w1, w2);

    cudaFuncSetAttribute(cce_mma_kernel,
                         cudaFuncAttributeMaxDynamicSharedMemorySize, SMEM_TOTAL);
    dim3 grid(OX / 2, 32, 2);                // (31, 32, 2)
    cce_mma_kernel<<<grid, 256, SMEM_TOTAL>>>(x, out);
}

// round 16
// speedup vs baseline: 1.4398x; 1.4398x over previous
#include <cuda_runtime.h>
#include <cuda_bf16.h>
#include <cstdint>

// ============================================================================
// ComplexConv2Deffangle via warp-level bf16 3-term split MMA (m16n8k16),
// 4-chunk cp.async pipeline, 3 blocks/SM, m4n2 warp split in MMA phase.
//   path0 (rot): depthwise 3x3 (w1^2/sum)  -> 1x1 (w2^2/sum)
//   path1 (abs): log(x+eps) -> depthwise (w1^2/rowsum) -> 1x1 (w2^2/rowsum) -> exp
// x: (32,2,64,64,64) f32, w1: (64,9), w2: (128,64) -> out: (32,2,128,62,62)
// Per block: D[128 och][128 n] = W[128][64] * V[64][128]; v = hi+lo bf16,
// D = Wh*Vh + Wh*Vl + Wl*Vh.
// ============================================================================

#define EPS 1e-6f
#define C_IN 64
#define C_OUT 128
#define HH 64
#define WW 64
#define OX 62
#define OY 62
#define LTOT (OX * OY)           // 3844

#define XCH 300                  // xin channel stride (floats), 1200 B
#define XRW 68                   // xin row stride (floats), 272 B

// smem byte offsets
#define OFF_BQ   0               // uint4[4*516]: B quads per chunk     33,024 B
#define OFF_X0   33024           // xin buf0 (16 ch x 4 rows)           19,200 B
#define OFF_X1   52224           // xin buf1                            19,200 B
#define OFF_W1S  71424           // float[64][9]                         2,304 B
#define SMEM_TOTAL 73728         // -> 3 blocks/SM (216 KB / 228 KB)

// A fragments pre-packed for m16n8k16.bf16, hi/lo interleaved:
// g_w2b[p][cc][kk][m_tile][lane][hl]; chunk g = cc*2 + kk covers ch g*16..+15
__device__ float4 g_w2b[2][2][2][8][32][2];
__device__ float  g_w1n[2][C_IN][9];

// ---------------------------------------------------------------------------
__device__ __forceinline__ uint32_t smem_u32(const void* p) {
    uint32_t a;
    asm("{ .reg .u64 t; cvta.to.shared.u64 t, %1; cvt.u32.u64 %0, t; }"
        : "=r"(a) : "l"(p));
    return a;
}
// returns bf16x2 {upper=hi_e, lower=lo_e}
__device__ __forceinline__ uint32_t pack_bf(float lo_e, float hi_e) {
    uint32_t d;
    asm("cvt.rn.bf16x2.f32 %0, %1, %2;" : "=r"(d) : "f"(hi_e), "f"(lo_e));
    return d;
}
__device__ __forceinline__ float bf16rn(float x) {
    uint32_t d;
    asm("cvt.rn.bf16x2.f32 %0, %1, %1;" : "=r"(d) : "f"(x));
    return __uint_as_float(d << 16);
}
__device__ __forceinline__ void mma_bf16(float* acc, uint32_t a0, uint32_t a1,
                                         uint32_t a2, uint32_t a3,
                                         uint32_t b0, uint32_t b1) {
    asm volatile(
        "mma.sync.aligned.m16n8k16.row.col.f32.bf16.bf16.f32 "
        "{%0,%1,%2,%3}, {%4,%5,%6,%7}, {%8,%9}, {%0,%1,%2,%3};"
        : "+f"(acc[0]), "+f"(acc[1]), "+f"(acc[2]), "+f"(acc[3])
        : "r"(a0), "r"(a1), "r"(a2), "r"(a3), "r"(b0), "r"(b1));
}
__device__ __forceinline__ void cp16(uint32_t dst, const void* src) {
    asm volatile("cp.async.cg.shared.global [%0], [%1], 16;"
                 :: "r"(dst), "l"(src) : "memory");
}
#define CP_COMMIT() asm volatile("cp.async.commit_group;" ::: "memory")
#define CP_WAIT(n)  asm volatile("cp.async.wait_group %0;" :: "n"(n) : "memory")

// xin addressing (floats): channel cl in 0..15, row rr, col f.
// shift (cl>>1)*4 makes 16B-columns a permutation per quarter-warp.
__device__ __forceinline__ int xoff(int cl, int rr, int f) {
    return cl * XCH + (cl >> 1) * 4 + rr * XRW + f;
}

// ---------------------------------------------------------------------------
// Prep kernel: normalize weights, bf16-split, pack mma A fragments.
// ---------------------------------------------------------------------------
__global__ void prep_weights_kernel(const float* __restrict__ w1,
                                    const float* __restrict__ w2) {
    __shared__ float red[256];
    __shared__ float s1_sh, s2_sh;
    __shared__ float s1r[C_IN];
    __shared__ float s2r[C_OUT];
    int tid = threadIdx.x;

    float a = 0.f;
    for (int i = tid; i < C_IN * 9; i += 256) { float t = w1[i]; a += t * t; }
    red[tid] = a; __syncthreads();
    for (int s = 128; s > 0; s >>= 1) { if (tid < s) red[tid] += red[tid + s]; __syncthreads(); }
    if (tid == 0) s1_sh = red[0];
    __syncthreads();

    a = 0.f;
    for (int i = tid; i < C_OUT * C_IN; i += 256) { float t = w2[i]; a += t * t; }
    red[tid] = a; __syncthreads();
    for (int s = 128; s > 0; s >>= 1) { if (tid < s) red[tid] += red[tid + s]; __syncthreads(); }
    if (tid == 0) s2_sh = red[0];

    if (tid < C_IN) {
        float s = 0.f;
        for (int k = 0; k < 9; k++) { float t = w1[tid * 9 + k]; s += t * t; }
        s1r[tid] = s;
    }
    if (tid < C_OUT) {
        float s = 0.f;
        for (int c = 0; c < C_IN; c++) { float t = w2[tid * C_IN + c]; s += t * t; }
        s2r[tid] = s;
    }
    __syncthreads();

    float inv_s1 = 1.f / s1_sh;
    float inv_s2 = 1.f / s2_sh;

    for (int i = tid; i < C_IN * 9; i += 256) {
        int c = i / 9;
        float t = w1[i]; float t2 = t * t;
        ((float*)g_w1n[0])[i] = t2 * inv_s1;
        ((float*)g_w1n[1])[i] = t2 / s1r[c];
    }

    // A fragments: j indexes (p, cc, kk, m_tile, lane)
    float4* flat = (float4*)g_w2b;
    for (int j = tid; j < 2048; j += 256) {
        int lane = j & 31;
        int wq   = (j >> 5) & 7;
        int kk   = (j >> 8) & 1;
        int cc   = (j >> 9) & 1;
        int p    = j >> 10;
        int qq = lane >> 2, rr2 = lane & 3;
        int cb = cc * 32 + kk * 16 + 2 * rr2;
        int ms[2] = {wq * 16 + qq, wq * 16 + qq + 8};
        uint32_t ah[4], al[4];
        #pragma unroll
        for (int i = 0; i < 4; i++) {
            int m  = ms[i & 1];
            int c0 = cb + (i >> 1) * 8;
            float t0 = w2[m * C_IN + c0];
            float t1 = w2[m * C_IN + c0 + 1];
            float v0 = (p == 0) ? t0 * t0 * inv_s2 : t0 * t0 / s2r[m];
            float v1 = (p == 0) ? t1 * t1 * inv_s2 : t1 * t1 / s2r[m];
            float h0 = bf16rn(v0), h1 = bf16rn(v1);
            ah[i] = pack_bf(h0, h1);           // lower = k even
            al[i] = pack_bf(v0 - h0, v1 - h1);
        }
        flat[j * 2 + 0] = make_float4(__uint_as_float(ah[0]), __uint_as_float(ah[1]),
                                      __uint_as_float(ah[2]), __uint_as_float(ah[3]));
        flat[j * 2 + 1] = make_float4(__uint_as_float(al[0]), __uint_as_float(al[1]),
                                      __uint_as_float(al[2]), __uint_as_float(al[3]));
    }
}

// ---------------------------------------------------------------------------
// Main kernel: grid (31 row-pairs, 32 batch, 2 path), 256 threads, 3 blk/SM.
// ---------------------------------------------------------------------------
__global__ __launch_bounds__(256, 3)
void cce_mma_kernel(const float* __restrict__ x, float* __restrict__ out) {
    extern __shared__ char smem[];
    const uint32_t sb = smem_u32(smem);
    uint4*  BQ4 = (uint4*)(smem + OFF_BQ);
    uint2*  BQ2 = (uint2*)(smem + OFF_BQ);
    float*  w1s = (float*)(smem + OFF_W1S);

    const int tid  = threadIdx.x;
    const int warp = tid >> 5;
    const int lane = tid & 31;
    const int q    = lane >> 2;              // groupID
    const int r    = lane & 3;               // threadInGroup
    const int r0   = blockIdx.x * 2;
    const int b    = blockIdx.y;
    const int p    = blockIdx.z;

    const float* xbase = x + (size_t)(b * 2 + p) * (C_IN * HH * WW) + r0 * WW;

    // ---- cp.async staging for chunk g into buffer (g&1) — BOTH paths ----
    auto issue_chunk = [&](int g) {
        const uint32_t xo = sb + ((g & 1) ? OFF_X1 : OFF_X0);
        const float* xc = xbase + (size_t)(g * 16) * (HH * WW);
        #pragma unroll
        for (int i = 0; i < 4; i++) {
            int idx = tid + i * 256;         // 0..1023 float4
            int cl = idx >> 6, qq = idx & 63;
            cp16(xo + (uint32_t)xoff(cl, qq >> 4, (qq & 15) * 4) * 4,
                 xc + (size_t)cl * (HH * WW) + qq * 4);
        }
        CP_COMMIT();
    };

    issue_chunk(0);
    issue_chunk(1);
    for (int i = tid; i < C_IN * 9; i += 256) w1s[i] = ((const float*)g_w1n[p])[i];

    // dw decomposition: hp = ch-offset half {0,8}, rp = r-slot, 4 cols
    const int hp  = tid & 1;
    const int rp  = (tid >> 1) & 3;
    const int nb  = tid >> 3;                // 0..31
    const int n0  = nb * 4;
    const int rl0 = n0 >> 6;
    const int l0  = n0 & 63;                 // 4-aligned

    // ========== phase 1: staging + depthwise, 4 chunks of 16 channels ======
    #pragma unroll
    for (int g = 0; g < 4; g++) {
        float* xin = (float*)(smem + ((g & 1) ? OFF_X1 : OFF_X0));

        if (g < 3) { CP_WAIT(1); } else { CP_WAIT(0); }
        __syncthreads();

        if (p == 1) {
            // in-place log transform
            #pragma unroll
            for (int i = 0; i < 4; i++) {
                int idx = tid + i * 256;
                int cl = idx >> 6, qq = idx & 63;
                float* pp = xin + xoff(cl, qq >> 4, (qq & 15) * 4);
                float4 v = *(float4*)pp;
                v.x = __logf(v.x + EPS); v.y = __logf(v.y + EPS);
                v.z = __logf(v.z + EPS); v.w = __logf(v.w + EPS);
                *(float4*)pp = v;
            }
            __syncthreads();
        }

        // depthwise 3x3: 2 channels x 4 cols per thread
        float dv[2][4];
        #pragma unroll
        for (int i = 0; i < 2; i++)
            #pragma unroll
            for (int j = 0; j < 4; j++) dv[i][j] = 0.f;

        #pragma unroll
        for (int ch2 = 0; ch2 < 2; ch2++) {
            int cl = 2 * rp + 8 * hp + ch2;
            const float* wc = w1s + (g * 16 + cl) * 9;
            float* av = dv[ch2];
            #pragma unroll
            for (int rr = 0; rr < 3; rr++) {
                const float* xr = xin + xoff(cl, rl0 + rr, 0);
                float4 u0 = *(const float4*)(xr + l0);
                float4 u1 = *(const float4*)(xr + l0 + 4);
                float f[8] = {u0.x,u0.y,u0.z,u0.w, u1.x,u1.y,u1.z,u1.w};
                float w0 = wc[rr * 3 + 0], w1v = wc[rr * 3 + 1], w2v = wc[rr * 3 + 2];
                #pragma unroll
                for (int ci = 0; ci < 4; ci++)
                    av[ci] = fmaf(f[ci], w0,
                             fmaf(f[ci + 1], w1v,
                             fmaf(f[ci + 2], w2v, av[ci])));
            }
        }
        // bf16 split + store half-quads {h01, l01} (hp selects quad half)
        #pragma unroll
        for (int ci = 0; ci < 4; ci++) {
            int n = n0 + ci;
            float v0 = dv[0][ci], v1 = dv[1][ci];
            float h0 = bf16rn(v0), h1 = bf16rn(v1);
            BQ2[(g * 516 + n * 4 + rp) * 2 + hp] =
                make_uint2(pack_bf(h0, h1), pack_bf(v0 - h0, v1 - h1));
        }
        __syncthreads();                     // buffer free + BQ[g] visible

        if (g < 2) issue_chunk(g + 2);
    }

    // ========== phase 2: MMA, m4n2 warp split, 2 rounds of 4 n-tiles =======
    // warp: mw = warp&3 -> och 32*mw..+31 (m-tiles 2mw, 2mw+1);
    //       nh = warp>>2 -> out row r0+nh (n 64*nh..+63).
    const int mw = warp & 3;
    const int nh = warp >> 2;
    float* obase = out + (size_t)(b * 2 + p) * (C_OUT * LTOT) + (size_t)r0 * OY;

    #pragma unroll
    for (int round = 0; round < 2; round++) {
        float acc[32];
        #pragma unroll
        for (int i = 0; i < 32; i++) acc[i] = 0.f;

        #pragma unroll
        for (int g = 0; g < 4; g++) {
            const float4* wgA = &g_w2b[p][g >> 1][g & 1][2 * mw][lane][0];
            const float4* wgB = &g_w2b[p][g >> 1][g & 1][2 * mw + 1][lane][0];
            float4 AH0 = wgA[0], AL0 = wgA[1];
            float4 AH1 = wgB[0], AL1 = wgB[1];
            uint32_t a0h = __float_as_uint(AH0.x), a1h = __float_as_uint(AH0.y);
            uint32_t a2h = __float_as_uint(AH0.z), a3h = __float_as_uint(AH0.w);
            uint32_t a0l = __float_as_uint(AL0.x), a1l = __float_as_uint(AL0.y);
            uint32_t a2l = __float_as_uint(AL0.z), a3l = __float_as_uint(AL0.w);
            uint32_t c0h = __float_as_uint(AH1.x), c1h = __float_as_uint(AH1.y);
            uint32_t c2h = __float_as_uint(AH1.z), c3h = __float_as_uint(AH1.w);
            uint32_t c0l = __float_as_uint(AL1.x), c1l = __float_as_uint(AL1.y);
            uint32_t c2l = __float_as_uint(AL1.z), c3l = __float_as_uint(AL1.w);
            const uint4* bq = BQ4 + g * 516 + (nh * 8 + round * 4) * 32 + q * 4 + r;
            #pragma unroll
            for (int t = 0; t < 4; t++) {
                uint4 B = bq[t * 32];
                mma_bf16(acc + t * 4,      a0h, a1h, a2h, a3h, B.x, B.z);
                mma_bf16(acc + t * 4,      a0h, a1h, a2h, a3h, B.y, B.w);
                mma_bf16(acc + t * 4,      a0l, a1l, a2l, a3l, B.x, B.z);
                mma_bf16(acc + 16 + t * 4, c0h, c1h, c2h, c3h, B.x, B.z);
                mma_bf16(acc + 16 + t * 4, c0h, c1h, c2h, c3h, B.y, B.w);
                mma_bf16(acc + 16 + t * 4, c0l, c1l, c2l, c3l, B.x, B.z);
            }
        }

        // epilogue: out row r0+nh, cols round*32 + t*8 + 2r
        #pragma unroll
        for (int tm2 = 0; tm2 < 2; tm2++) {
            #pragma unroll
            for (int t = 0; t < 4; t++) {
                int colb = round * 32 + t * 8 + 2 * r;
                if (colb < OY) {
                    int m = 32 * mw + 16 * tm2 + q;
                    float2 v0 = make_float2(acc[tm2 * 16 + t * 4 + 0],
                                            acc[tm2 * 16 + t * 4 + 1]);
                    float2 v1 = make_float2(acc[tm2 * 16 + t * 4 + 2],
                                            acc[tm2 * 16 + t * 4 + 3]);
                    if (p == 1) {
                        v0.x = __expf(v0.x); v0.y = __expf(v0.y);
                        v1.x = __expf(v1.x); v1.y = __expf(v1.y);
                    }
                    float* addr = obase + nh * OY + colb;
                    *(float2*)(addr + (size_t)m * LTOT)       = v0;
                    *(float2*)(addr + (size_t)(m + 8) * LTOT) = v1;
                }
            }
        }
    }
}

// ---------------------------------------------------------------------------
extern "C" void kernel_launch(void* const* d_in, const int* in_sizes, int n_in,
                              void* d_out, int out_size) {
    const float* x  = (const float*)d_in[0];
    const float* w1 = (const float*)d_in[1];
    const float* w2 = (const float*)d_in[2];
    float* out = (float*)d_out;

    prep_weights_kernel<<<1, 256>>>(w1, w2);

    cudaFuncSetAttribute(cce_mma_kernel,
                         cudaFuncAttributeMaxDynamicSharedMemorySize, SMEM_TOTAL);
    dim3 grid(OX / 2, 32, 2);                // (31, 32, 2)
    cce_mma_kernel<<<grid, 256, SMEM_TOTAL>>>(x, out);
}

// round 17
// speedup vs baseline: 1.7718x; 1.2306x over previous
#include <cuda_runtime.h>
#include <cuda_bf16.h>
#include <cuda_fp16.h>
#include <cstdint>

// ============================================================================
// ComplexConv2Deffangle via warp-level SINGLE-PASS fp16 MMA (m16n8k16),
// 4-chunk cp.async pipeline, 3 blocks/SM, m4n2 warp split in MMA phase.
//   path0 (rot): depthwise 3x3 (w1^2/sum)  -> 1x1 (w2^2/sum)
//   path1 (abs): log(x+eps) -> depthwise (w1^2/rowsum) -> 1x1 (w2^2/rowsum) -> exp
// x: (32,2,64,64,64) f32, w1: (64,9), w2: (128,64) -> out: (32,2,128,62,62)
// Per block: D[128 och][128 n] = W[128][64] * V[64][128] in fp16 (f32 acc).
// fp16 rounding gives ~2e-4 norm rel err vs the 1e-3 threshold.
// ============================================================================

#define EPS 1e-6f
#define C_IN 64
#define C_OUT 128
#define HH 64
#define WW 64
#define OX 62
#define OY 62
#define LTOT (OX * OY)           // 3844

#define XCH 300                  // xin channel stride (floats), 1200 B
#define XRW 68                   // xin row stride (floats), 272 B

// smem byte offsets
#define OFF_BQ   0               // uint[4*1032]: fp16 B pairs per chunk 16,512 B
#define OFF_X0   16512           // xin buf0 (16 ch x 4 rows)            19,200 B
#define OFF_X1   35712           // xin buf1                             19,200 B
#define OFF_W1S  54912           // float[64][9]                          2,304 B
#define SMEM_TOTAL 57216         // -> 3 blocks/SM with regs to spare

// A fragments pre-packed for m16n8k16.f16:
// g_w2h[p][cc][kk][m_tile][lane] = uint4 {a0,a1,a2,a3}; chunk g = cc*2+kk.
__device__ uint4 g_w2h[2][2][2][8][32];
__device__ float g_w1n[2][C_IN][9];

// ---------------------------------------------------------------------------
__device__ __forceinline__ uint32_t smem_u32(const void* p) {
    uint32_t a;
    asm("{ .reg .u64 t; cvta.to.shared.u64 t, %1; cvt.u32.u64 %0, t; }"
        : "=r"(a) : "l"(p));
    return a;
}
// returns fp16x2 {upper=hi_e, lower=lo_e}
__device__ __forceinline__ uint32_t pack_h(float lo_e, float hi_e) {
    uint32_t d;
    asm("cvt.rn.f16x2.f32 %0, %1, %2;" : "=r"(d) : "f"(hi_e), "f"(lo_e));
    return d;
}
__device__ __forceinline__ void mma_f16(float* acc, uint32_t a0, uint32_t a1,
                                        uint32_t a2, uint32_t a3,
                                        uint32_t b0, uint32_t b1) {
    asm volatile(
        "mma.sync.aligned.m16n8k16.row.col.f32.f16.f16.f32 "
        "{%0,%1,%2,%3}, {%4,%5,%6,%7}, {%8,%9}, {%0,%1,%2,%3};"
        : "+f"(acc[0]), "+f"(acc[1]), "+f"(acc[2]), "+f"(acc[3])
        : "r"(a0), "r"(a1), "r"(a2), "r"(a3), "r"(b0), "r"(b1));
}
__device__ __forceinline__ void cp16(uint32_t dst, const void* src) {
    asm volatile("cp.async.cg.shared.global [%0], [%1], 16;"
                 :: "r"(dst), "l"(src) : "memory");
}
#define CP_COMMIT() asm volatile("cp.async.commit_group;" ::: "memory")
#define CP_WAIT(n)  asm volatile("cp.async.wait_group %0;" :: "n"(n) : "memory")

// xin addressing (floats): channel cl in 0..15, row rr, col f.
// shift (cl>>1)*4 makes 16B-columns a permutation per quarter-warp.
__device__ __forceinline__ int xoff(int cl, int rr, int f) {
    return cl * XCH + (cl >> 1) * 4 + rr * XRW + f;
}

// ---------------------------------------------------------------------------
// Prep kernel: normalize weights, pack fp16 mma A fragments.
// ---------------------------------------------------------------------------
__global__ void prep_weights_kernel(const float* __restrict__ w1,
                                    const float* __restrict__ w2) {
    __shared__ float red[256];
    __shared__ float s1_sh, s2_sh;
    __shared__ float s1r[C_IN];
    __shared__ float s2r[C_OUT];
    int tid = threadIdx.x;

    float a = 0.f;
    for (int i = tid; i < C_IN * 9; i += 256) { float t = w1[i]; a += t * t; }
    red[tid] = a; __syncthreads();
    for (int s = 128; s > 0; s >>= 1) { if (tid < s) red[tid] += red[tid + s]; __syncthreads(); }
    if (tid == 0) s1_sh = red[0];
    __syncthreads();

    a = 0.f;
    for (int i = tid; i < C_OUT * C_IN; i += 256) { float t = w2[i]; a += t * t; }
    red[tid] = a; __syncthreads();
    for (int s = 128; s > 0; s >>= 1) { if (tid < s) red[tid] += red[tid + s]; __syncthreads(); }
    if (tid == 0) s2_sh = red[0];

    if (tid < C_IN) {
        float s = 0.f;
        for (int k = 0; k < 9; k++) { float t = w1[tid * 9 + k]; s += t * t; }
        s1r[tid] = s;
    }
    if (tid < C_OUT) {
        float s = 0.f;
        for (int c = 0; c < C_IN; c++) { float t = w2[tid * C_IN + c]; s += t * t; }
        s2r[tid] = s;
    }
    __syncthreads();

    float inv_s1 = 1.f / s1_sh;
    float inv_s2 = 1.f / s2_sh;

    for (int i = tid; i < C_IN * 9; i += 256) {
        int c = i / 9;
        float t = w1[i]; float t2 = t * t;
        ((float*)g_w1n[0])[i] = t2 * inv_s1;
        ((float*)g_w1n[1])[i] = t2 / s1r[c];
    }

    // A fragments: j indexes (p, cc, kk, m_tile, lane)
    uint4* flat = (uint4*)g_w2h;
    for (int j = tid; j < 2048; j += 256) {
        int lane = j & 31;
        int wq   = (j >> 5) & 7;
        int kk   = (j >> 8) & 1;
        int cc   = (j >> 9) & 1;
        int p    = j >> 10;
        int qq = lane >> 2, rr2 = lane & 3;
        int cb = cc * 32 + kk * 16 + 2 * rr2;
        int ms[2] = {wq * 16 + qq, wq * 16 + qq + 8};
        uint32_t ah[4];
        #pragma unroll
        for (int i = 0; i < 4; i++) {
            int m  = ms[i & 1];
            int c0 = cb + (i >> 1) * 8;
            float t0 = w2[m * C_IN + c0];
            float t1 = w2[m * C_IN + c0 + 1];
            float v0 = (p == 0) ? t0 * t0 * inv_s2 : t0 * t0 / s2r[m];
            float v1 = (p == 0) ? t1 * t1 * inv_s2 : t1 * t1 / s2r[m];
            ah[i] = pack_h(v0, v1);            // lower = k even
        }
        flat[j] = make_uint4(ah[0], ah[1], ah[2], ah[3]);
    }
}

// ---------------------------------------------------------------------------
// Main kernel: grid (31 row-pairs, 32 batch, 2 path), 256 threads, 3 blk/SM.
// ---------------------------------------------------------------------------
__global__ __launch_bounds__(256, 3)
void cce_mma_kernel(const float* __restrict__ x, float* __restrict__ out) {
    extern __shared__ char smem[];
    const uint32_t sb = smem_u32(smem);
    uint32_t* BQu  = (uint32_t*)(smem + OFF_BQ);
    uint2*    BQu2 = (uint2*)(smem + OFF_BQ);
    float*    w1s  = (float*)(smem + OFF_W1S);

    const int tid  = threadIdx.x;
    const int warp = tid >> 5;
    const int lane = tid & 31;
    const int q    = lane >> 2;              // groupID
    const int r    = lane & 3;               // threadInGroup
    const int r0   = blockIdx.x * 2;
    const int b    = blockIdx.y;
    const int p    = blockIdx.z;

    const float* xbase = x + (size_t)(b * 2 + p) * (C_IN * HH * WW) + r0 * WW;

    // ---- cp.async staging for chunk g into buffer (g&1) ----
    auto issue_chunk = [&](int g) {
        const uint32_t xo = sb + ((g & 1) ? OFF_X1 : OFF_X0);
        const float* xc = xbase + (size_t)(g * 16) * (HH * WW);
        #pragma unroll
        for (int i = 0; i < 4; i++) {
            int idx = tid + i * 256;         // 0..1023 float4
            int cl = idx >> 6, qq = idx & 63;
            cp16(xo + (uint32_t)xoff(cl, qq >> 4, (qq & 15) * 4) * 4,
                 xc + (size_t)cl * (HH * WW) + qq * 4);
        }
        CP_COMMIT();
    };

    issue_chunk(0);
    issue_chunk(1);
    for (int i = tid; i < C_IN * 9; i += 256) w1s[i] = ((const float*)g_w1n[p])[i];

    // dw decomposition: hp = ch-offset half {0,8}, rp = r-slot, 4 cols
    const int hp  = tid & 1;
    const int rp  = (tid >> 1) & 3;
    const int nb  = tid >> 3;                // 0..31
    const int n0  = nb * 4;
    const int rl0 = n0 >> 6;
    const int l0  = n0 & 63;                 // 4-aligned

    // ========== phase 1: staging + depthwise, 4 chunks of 16 channels ======
    #pragma unroll
    for (int g = 0; g < 4; g++) {
        float* xin = (float*)(smem + ((g & 1) ? OFF_X1 : OFF_X0));

        if (g < 3) { CP_WAIT(1); } else { CP_WAIT(0); }
        __syncthreads();

        if (p == 1) {
            // in-place log transform
            #pragma unroll
            for (int i = 0; i < 4; i++) {
                int idx = tid + i * 256;
                int cl = idx >> 6, qq = idx & 63;
                float* pp = xin + xoff(cl, qq >> 4, (qq & 15) * 4);
                float4 v = *(float4*)pp;
                v.x = __logf(v.x + EPS); v.y = __logf(v.y + EPS);
                v.z = __logf(v.z + EPS); v.w = __logf(v.w + EPS);
                *(float4*)pp = v;
            }
            __syncthreads();
        }

        // depthwise 3x3: 2 channels x 4 cols per thread
        float dv[2][4];
        #pragma unroll
        for (int i = 0; i < 2; i++)
            #pragma unroll
            for (int j = 0; j < 4; j++) dv[i][j] = 0.f;

        #pragma unroll
        for (int ch2 = 0; ch2 < 2; ch2++) {
            int cl = 2 * rp + 8 * hp + ch2;
            const float* wc = w1s + (g * 16 + cl) * 9;
            float* av = dv[ch2];
            #pragma unroll
            for (int rr = 0; rr < 3; rr++) {
                const float* xr = xin + xoff(cl, rl0 + rr, 0);
                float4 u0 = *(const float4*)(xr + l0);
                float4 u1 = *(const float4*)(xr + l0 + 4);
                float f[8] = {u0.x,u0.y,u0.z,u0.w, u1.x,u1.y,u1.z,u1.w};
                float w0 = wc[rr * 3 + 0], w1v = wc[rr * 3 + 1], w2v = wc[rr * 3 + 2];
                #pragma unroll
                for (int ci = 0; ci < 4; ci++)
                    av[ci] = fmaf(f[ci], w0,
                             fmaf(f[ci + 1], w1v,
                             fmaf(f[ci + 2], w2v, av[ci])));
            }
        }
        // fp16 pack + store B pairs; entry (n, rp, hp): half2 {ch, ch+1}
        #pragma unroll
        for (int ci = 0; ci < 4; ci++) {
            int n = n0 + ci;
            BQu[g * 1032 + n * 8 + rp * 2 + hp] = pack_h(dv[0][ci], dv[1][ci]);
        }
        __syncthreads();                     // buffer free + BQ[g] visible

        if (g < 2) issue_chunk(g + 2);
    }

    // ========== phase 2: MMA, m4n2 warp split, 2 rounds of 4 n-tiles =======
    // warp: mw = warp&3 -> och 32*mw..+31 (m-tiles 2mw, 2mw+1);
    //       nh = warp>>2 -> out row r0+nh (n 64*nh..+63).
    const int mw = warp & 3;
    const int nh = warp >> 2;
    float* obase = out + (size_t)(b * 2 + p) * (C_OUT * LTOT) + (size_t)r0 * OY;

    #pragma unroll
    for (int round = 0; round < 2; round++) {
        float acc[32];
        #pragma unroll
        for (int i = 0; i < 32; i++) acc[i] = 0.f;

        #pragma unroll
        for (int g = 0; g < 4; g++) {
            uint4 A0 = g_w2h[p][g >> 1][g & 1][2 * mw][lane];
            uint4 A1 = g_w2h[p][g >> 1][g & 1][2 * mw + 1][lane];
            const uint2* bq = BQu2 + g * 516 + (nh * 8 + round * 4) * 32 + q * 4 + r;
            #pragma unroll
            for (int t = 0; t < 4; t++) {
                uint2 B = bq[t * 32];        // b0 = k0..1, b1 = k8..9
                mma_f16(acc + t * 4,      A0.x, A0.y, A0.z, A0.w, B.x, B.y);
                mma_f16(acc + 16 + t * 4, A1.x, A1.y, A1.z, A1.w, B.x, B.y);
            }
        }

        // epilogue: out row r0+nh, cols round*32 + t*8 + 2r
        #pragma unroll
        for (int tm2 = 0; tm2 < 2; tm2++) {
            #pragma unroll
            for (int t = 0; t < 4; t++) {
                int colb = round * 32 + t * 8 + 2 * r;
                if (colb < OY) {
                    int m = 32 * mw + 16 * tm2 + q;
                    float2 v0 = make_float2(acc[tm2 * 16 + t * 4 + 0],
                                            acc[tm2 * 16 + t * 4 + 1]);
                    float2 v1 = make_float2(acc[tm2 * 16 + t * 4 + 2],
                                            acc[tm2 * 16 + t * 4 + 3]);
                    if (p == 1) {
                        v0.x = __expf(v0.x); v0.y = __expf(v0.y);
                        v1.x = __expf(v1.x); v1.y = __expf(v1.y);
                    }
                    float* addr = obase + nh * OY + colb;
                    *(float2*)(addr + (size_t)m * LTOT)       = v0;
                    *(float2*)(addr + (size_t)(m + 8) * LTOT) = v1;
                }
            }
        }
    }
}

// ---------------------------------------------------------------------------
extern "C" void kernel_launch(void* const* d_in, const int* in_sizes, int n_in,
                              void* d_out, int out_size) {
    const float* x  = (const float*)d_in[0];
    const float* w1 = (const float*)d_in[1];
    const float* w2 = (const float*)d_in[2];
    float* out = (float*)d_out;

    prep_weights_kernel<<<1, 256>>>(w1, w2);

    cudaFuncSetAttribute(cce_mma_kernel,
                         cudaFuncAttributeMaxDynamicSharedMemorySize, SMEM_TOTAL);
    dim3 grid(OX / 2, 32, 2);                // (31, 32, 2)
    cce_mma_kernel<<<grid, 256, SMEM_TOTAL>>>(x, out);
}